// round 9
// baseline (speedup 1.0000x reference)
#include <cuda_runtime.h>
#include <cuda_fp16.h>

#define NN 100000
#define NE 1600000
#define F_IN 128
#define HID 64
#define N_CLS 16

// ---------------- device scratch (allocation-free per rules) ----------------
__device__ int    g_cnt[NN];
__device__ int    g_rowptr[NN];
__device__ int    g_cursor[NN];
__device__ int    g_col[NE];
__device__ float  g_dinv[NN];
__device__ __half g_zh[NN * HID];     // dinv-scaled XW (fp16)
__device__ __half g_hh[NN * HID];     // hidden activations (fp16)
__device__ __half g_wt1[HID * F_IN];  // W1^T fp16 [64][128]
__device__ __half g_wt2[HID * HID];   // W2^T fp16 [64][64]
__device__ __half g_wt3[N_CLS * HID]; // W3^T fp16 [16][64]
__device__ int    g_blksum[128];
__device__ int    g_is64;

#define LDSM4(r0, r1, r2, r3, addr) \
    asm volatile("ldmatrix.sync.aligned.m8n8.x4.shared.b16 {%0,%1,%2,%3}, [%4];" \
                 : "=r"(r0), "=r"(r1), "=r"(r2), "=r"(r3) : "r"(addr))

#define MMA16816(c, a0, a1, a2, a3, b0, b1) \
    asm volatile("mma.sync.aligned.m16n8k16.row.col.f32.f16.f16.f32 " \
                 "{%0,%1,%2,%3}, {%4,%5,%6,%7}, {%8,%9}, {%0,%1,%2,%3};" \
                 : "+f"(c[0]), "+f"(c[1]), "+f"(c[2]), "+f"(c[3]) \
                 : "r"(a0), "r"(a1), "r"(a2), "r"(a3), "r"(b0), "r"(b1))

// ---------------- fused prep: zero counters + dtype detect + weight transpose
__global__ void k_prep(const int* __restrict__ ei32,
                       const float* __restrict__ W1, const float* __restrict__ W2,
                       const float* __restrict__ W3) {
    int i = blockIdx.x * blockDim.x + threadIdx.x;
    if (i < NN) g_cnt[i] = 0;
    if (i < HID * F_IN) {
        int n = i / F_IN, k = i % F_IN;
        g_wt1[n * F_IN + k] = __float2half(W1[k * HID + n]);
    } else if (i < HID * F_IN + HID * HID) {
        int j = i - HID * F_IN;
        int n = j / HID, k = j % HID;
        g_wt2[n * HID + k] = __float2half(W2[k * HID + n]);
    } else if (i < HID * F_IN + HID * HID + N_CLS * HID) {
        int j = i - HID * F_IN - HID * HID;
        int n = j / HID, k = j % HID;
        g_wt3[n * HID + k] = __float2half(W3[k * N_CLS + n]);
    }
    // int64-vs-int32 detect: high words of first 512 int64 entries all zero?
    if (blockIdx.x == 0 && threadIdx.x < 32) {
        int t = threadIdx.x;
        int nz = 0;
        for (int q = t; q < 512; q += 32) nz |= ei32[2 * q + 1];
        #pragma unroll
        for (int o = 16; o; o >>= 1) nz |= __shfl_xor_sync(0xffffffffu, nz, o);
        if (t == 0) g_is64 = (nz == 0) ? 1 : 0;
    }
}

// ---------------- degree count: 4 edges per thread, vector loads ------------
__global__ void k_count(const void* __restrict__ ei) {
    int i = blockIdx.x * blockDim.x + threadIdx.x;   // i < NE/4
    if (i < NE / 4) {
        int d0, d1, d2, d3;
        if (g_is64) {
            const longlong2* p = (const longlong2*)((const long long*)ei + NE) + i * 2;
            longlong2 v0 = p[0], v1 = p[1];
            d0 = (int)v0.x; d1 = (int)v0.y; d2 = (int)v1.x; d3 = (int)v1.y;
        } else {
            int4 v = ((const int4*)((const int*)ei + NE))[i];
            d0 = v.x; d1 = v.y; d2 = v.z; d3 = v.w;
        }
        atomicAdd(&g_cnt[d0], 1);
        atomicAdd(&g_cnt[d1], 1);
        atomicAdd(&g_cnt[d2], 1);
        atomicAdd(&g_cnt[d3], 1);
    }
}

__global__ void k_scan1() {
    __shared__ int wsum[32];
    int t = threadIdx.x, i = blockIdx.x * 1024 + t;
    int lane = t & 31, wid = t >> 5;
    int v = (i < NN) ? g_cnt[i] : 0;
    int s = v;
    #pragma unroll
    for (int o = 1; o < 32; o <<= 1) {
        int n = __shfl_up_sync(0xffffffffu, s, o);
        if (lane >= o) s += n;
    }
    if (lane == 31) wsum[wid] = s;
    __syncthreads();
    if (t < 32) {
        int w = wsum[t];
        int sc = w;
        #pragma unroll
        for (int o = 1; o < 32; o <<= 1) {
            int n = __shfl_up_sync(0xffffffffu, sc, o);
            if (t >= o) sc += n;
        }
        wsum[t] = sc - w;
        if (t == 31) g_blksum[blockIdx.x] = sc;
    }
    __syncthreads();
    if (i < NN) g_rowptr[i] = wsum[wid] + s - v;
}

__global__ void k_scan2(int nb) {
    __shared__ int s[128];
    int t = threadIdx.x;
    int v = (t < nb) ? g_blksum[t] : 0;
    s[t] = v; __syncthreads();
    #pragma unroll
    for (int off = 1; off < 128; off <<= 1) {
        int x = (t >= off) ? s[t - off] : 0;
        __syncthreads();
        s[t] += x;
        __syncthreads();
    }
    if (t < nb) g_blksum[t] = s[t] - v;
}

__global__ void k_scan3() {
    int i = blockIdx.x * blockDim.x + threadIdx.x;
    if (i < NN) {
        int rp = g_rowptr[i] + g_blksum[i >> 10];
        g_rowptr[i] = rp;
        g_cursor[i] = rp;
        g_dinv[i] = rsqrtf((float)(g_cnt[i] + 1));
    }
}

// ---------------- CSR fill: 4 edges per thread, vector loads ----------------
__global__ void k_fill(const void* __restrict__ ei) {
    int i = blockIdx.x * blockDim.x + threadIdx.x;   // i < NE/4
    if (i < NE / 4) {
        int s0, s1, s2, s3, d0, d1, d2, d3;
        if (g_is64) {
            const longlong2* ps = (const longlong2*)ei + i * 2;
            const longlong2* pd = (const longlong2*)((const long long*)ei + NE) + i * 2;
            longlong2 a0 = ps[0], a1 = ps[1], b0 = pd[0], b1 = pd[1];
            s0 = (int)a0.x; s1 = (int)a0.y; s2 = (int)a1.x; s3 = (int)a1.y;
            d0 = (int)b0.x; d1 = (int)b0.y; d2 = (int)b1.x; d3 = (int)b1.y;
        } else {
            int4 a = ((const int4*)ei)[i];
            int4 b = ((const int4*)((const int*)ei + NE))[i];
            s0 = a.x; s1 = a.y; s2 = a.z; s3 = a.w;
            d0 = b.x; d1 = b.y; d2 = b.z; d3 = b.w;
        }
        g_col[atomicAdd(&g_cursor[d0], 1)] = s0;
        g_col[atomicAdd(&g_cursor[d1], 1)] = s1;
        g_col[atomicAdd(&g_cursor[d2], 1)] = s2;
        g_col[atomicAdd(&g_cursor[d3], 1)] = s3;
    }
}

// ---------------- tensor-core GEMM: Z = half( dinv ⊙ (X @ W) ) --------------
template<int K, int COLS, bool IN_HALF>
__global__ void k_mgemm(const void* __restrict__ Xv, const __half* __restrict__ Wt,
                        __half* __restrict__ Z) {
    constexpr int ROWS = 128, NT = 256, KP = K + 8, SEG = K / 8;
    constexpr int NT2 = COLS / 16;
    extern __shared__ __half sh[];
    __half* Xs = sh;                 // ROWS * KP
    __half* Ws = sh + ROWS * KP;     // COLS * KP

    int tid  = threadIdx.x;
    int row0 = blockIdx.x * ROWS;

    for (int idx = tid; idx < ROWS * SEG; idx += NT) {
        int r = idx / SEG, s = idx % SEG;
        int gr = row0 + r;
        int4 v;
        if (gr < NN) {
            if (IN_HALF) {
                v = *(const int4*)((const __half*)Xv + (size_t)gr * K + s * 8);
            } else {
                const float* xp = (const float*)Xv + (size_t)gr * K + s * 8;
                float4 f0 = *(const float4*)xp;
                float4 f1 = *(const float4*)(xp + 4);
                __half2 h0 = __floats2half2_rn(f0.x, f0.y);
                __half2 h1 = __floats2half2_rn(f0.z, f0.w);
                __half2 h2 = __floats2half2_rn(f1.x, f1.y);
                __half2 h3 = __floats2half2_rn(f1.z, f1.w);
                v.x = *(int*)&h0; v.y = *(int*)&h1; v.z = *(int*)&h2; v.w = *(int*)&h3;
            }
        } else {
            v = make_int4(0, 0, 0, 0);
        }
        *(int4*)&Xs[r * KP + s * 8] = v;
    }
    for (int idx = tid; idx < COLS * SEG; idx += NT) {
        int n = idx / SEG, s = idx % SEG;
        *(int4*)&Ws[n * KP + s * 8] = *(const int4*)&Wt[n * K + s * 8];
    }
    __syncthreads();

    int lane = tid & 31, w = tid >> 5;
    int r0   = w * 16;
    int lrow = lane & 7, grp = lane >> 3;

    float c[COLS / 8][4];
    #pragma unroll
    for (int t = 0; t < COLS / 8; t++)
        #pragma unroll
        for (int q = 0; q < 4; q++) c[t][q] = 0.f;

    unsigned a_base = (unsigned)__cvta_generic_to_shared(
        &Xs[(r0 + lrow + 8 * (grp & 1)) * KP + 8 * (grp >> 1)]);
    unsigned b_base[NT2];
    #pragma unroll
    for (int p = 0; p < NT2; p++)
        b_base[p] = (unsigned)__cvta_generic_to_shared(
            &Ws[(p * 16 + lrow + 8 * (grp >> 1)) * KP + 8 * (grp & 1)]);

    #pragma unroll
    for (int kc = 0; kc < K; kc += 16) {
        unsigned a0, a1, a2, a3;
        LDSM4(a0, a1, a2, a3, a_base + kc * 2);
        #pragma unroll
        for (int p = 0; p < NT2; p++) {
            unsigned b0, b1, b2, b3;
            LDSM4(b0, b1, b2, b3, b_base[p] + kc * 2);
            MMA16816(c[2 * p],     a0, a1, a2, a3, b0, b1);
            MMA16816(c[2 * p + 1], a0, a1, a2, a3, b2, b3);
        }
    }

    int row1 = row0 + r0 + (lane >> 2);
    int row2 = row1 + 8;
    int colp = (lane & 3) * 2;
    float d1 = (row1 < NN) ? g_dinv[row1] : 0.f;
    float d2 = (row2 < NN) ? g_dinv[row2] : 0.f;
    #pragma unroll
    for (int t = 0; t < COLS / 8; t++) {
        int col = t * 8 + colp;
        if (row1 < NN) {
            __half2 h = __floats2half2_rn(c[t][0] * d1, c[t][1] * d1);
            *(__half2*)&Z[(size_t)row1 * COLS + col] = h;
        }
        if (row2 < NN) {
            __half2 h = __floats2half2_rn(c[t][2] * d2, c[t][3] * d2);
            *(__half2*)&Z[(size_t)row2 * COLS + col] = h;
        }
    }
}

// ---------------- aggregation: O[i] = act(dinv[i]*(Z[i] + sum_nbr Z[src]) + b)
// warp per node; 4 groups of 8 lanes; 2 gather loads in flight per group.
template<bool RELU>
__global__ void k_agg64(const __half* __restrict__ Z, const float* __restrict__ bias,
                        __half* __restrict__ O) {
    int w = (blockIdx.x * blockDim.x + threadIdx.x) >> 5;
    int lane = threadIdx.x & 31;
    int grp = lane >> 3;          // edge group 0..3
    int sub = lane & 7;           // column octet 0..7
    int start = g_rowptr[w], m = g_cnt[w];

    float acc[8];
    if (grp == 0) {               // self loop handled by group 0
        int4 v = *(const int4*)&Z[(size_t)w * 64 + sub * 8];
        __half2* h = (__half2*)&v;
        #pragma unroll
        for (int q = 0; q < 4; q++) {
            float2 f = __half22float2(h[q]);
            acc[2 * q] = f.x; acc[2 * q + 1] = f.y;
        }
    } else {
        #pragma unroll
        for (int q = 0; q < 8; q++) acc[q] = 0.f;
    }

    for (int base = 0; base < m; base += 32) {
        int rem = m - base;
        int idx = (lane < rem) ? g_col[start + base + lane] : 0;
        int lim = rem < 32 ? rem : 32;
        for (int j = 0; j < lim; j += 8) {
            int e0 = j + grp, e1 = j + 4 + grp;
            int s0 = __shfl_sync(0xffffffffu, idx, e0 & 31);
            int s1 = __shfl_sync(0xffffffffu, idx, e1 & 31);
            bool p0 = e0 < lim, p1 = e1 < lim;
            int4 v0 = make_int4(0, 0, 0, 0), v1 = make_int4(0, 0, 0, 0);
            if (p0) v0 = *(const int4*)&Z[(size_t)s0 * 64 + sub * 8];
            if (p1) v1 = *(const int4*)&Z[(size_t)s1 * 64 + sub * 8];
            __half2* h0 = (__half2*)&v0;
            __half2* h1 = (__half2*)&v1;
            #pragma unroll
            for (int q = 0; q < 4; q++) {
                float2 f0 = __half22float2(h0[q]);
                float2 f1 = __half22float2(h1[q]);
                acc[2 * q]     += f0.x + f1.x;
                acc[2 * q + 1] += f0.y + f1.y;
            }
        }
    }
    // combine the 4 edge groups
    #pragma unroll
    for (int q = 0; q < 8; q++) {
        acc[q] += __shfl_xor_sync(0xffffffffu, acc[q], 8);
        acc[q] += __shfl_xor_sync(0xffffffffu, acc[q], 16);
    }
    if (grp == 0) {
        float d = g_dinv[w];
        __half2 hv[4];
        #pragma unroll
        for (int q = 0; q < 4; q++) {
            float ox = fmaf(d, acc[2 * q],     bias[sub * 8 + 2 * q]);
            float oy = fmaf(d, acc[2 * q + 1], bias[sub * 8 + 2 * q + 1]);
            if (RELU) { ox = fmaxf(ox, 0.f); oy = fmaxf(oy, 0.f); }
            hv[q] = __floats2half2_rn(ox, oy);
        }
        *(int4*)&O[(size_t)w * 64 + sub * 8] = *(int4*)hv;
    }
}

// 16-col final layer: warp per node; 16 groups of 2 lanes; 2 loads in flight.
__global__ void k_agg16(const __half* __restrict__ Z, const float* __restrict__ bias,
                        float* __restrict__ O) {
    int w = (blockIdx.x * blockDim.x + threadIdx.x) >> 5;
    int lane = threadIdx.x & 31;
    int grp = lane >> 1;          // edge group 0..15
    int sub = lane & 1;           // column octet 0..1
    int start = g_rowptr[w], m = g_cnt[w];

    float acc[8];
    if (grp == 0) {               // self loop
        int4 v = *(const int4*)&Z[(size_t)w * 16 + sub * 8];
        __half2* h = (__half2*)&v;
        #pragma unroll
        for (int q = 0; q < 4; q++) {
            float2 f = __half22float2(h[q]);
            acc[2 * q] = f.x; acc[2 * q + 1] = f.y;
        }
    } else {
        #pragma unroll
        for (int q = 0; q < 8; q++) acc[q] = 0.f;
    }

    for (int base = 0; base < m; base += 32) {
        int rem = m - base;
        int idx = (lane < rem) ? g_col[start + base + lane] : 0;
        int lim = rem < 32 ? rem : 32;
        for (int j = 0; j < lim; j += 32) {
            int e0 = j + grp, e1 = j + 16 + grp;
            int s0 = __shfl_sync(0xffffffffu, idx, e0 & 31);
            int s1 = __shfl_sync(0xffffffffu, idx, e1 & 31);
            bool p0 = e0 < lim, p1 = e1 < lim;
            int4 v0 = make_int4(0, 0, 0, 0), v1 = make_int4(0, 0, 0, 0);
            if (p0) v0 = *(const int4*)&Z[(size_t)s0 * 16 + sub * 8];
            if (p1) v1 = *(const int4*)&Z[(size_t)s1 * 16 + sub * 8];
            __half2* h0 = (__half2*)&v0;
            __half2* h1 = (__half2*)&v1;
            #pragma unroll
            for (int q = 0; q < 4; q++) {
                float2 f0 = __half22float2(h0[q]);
                float2 f1 = __half22float2(h1[q]);
                acc[2 * q]     += f0.x + f1.x;
                acc[2 * q + 1] += f0.y + f1.y;
            }
        }
    }
    // combine 16 edge groups
    #pragma unroll
    for (int q = 0; q < 8; q++) {
        acc[q] += __shfl_xor_sync(0xffffffffu, acc[q], 2);
        acc[q] += __shfl_xor_sync(0xffffffffu, acc[q], 4);
        acc[q] += __shfl_xor_sync(0xffffffffu, acc[q], 8);
        acc[q] += __shfl_xor_sync(0xffffffffu, acc[q], 16);
    }
    if (grp == 0) {
        float d = g_dinv[w];
        float o[8];
        #pragma unroll
        for (int q = 0; q < 8; q++) o[q] = fmaf(d, acc[q], bias[sub * 8 + q]);
        float4* op = (float4*)&O[(size_t)w * 16 + sub * 8];
        op[0] = make_float4(o[0], o[1], o[2], o[3]);
        op[1] = make_float4(o[4], o[5], o[6], o[7]);
    }
}

// ---------------- launch ----------------
extern "C" void kernel_launch(void* const* d_in, const int* in_sizes, int n_in,
                              void* d_out, int out_size) {
    const float* x  = (const float*)d_in[0];
    const void*  ei = d_in[1];
    const float* W1 = (const float*)d_in[2];
    const float* b1 = (const float*)d_in[3];
    const float* W2 = (const float*)d_in[4];
    const float* b2 = (const float*)d_in[5];
    const float* W3 = (const float*)d_in[6];
    const float* b3 = (const float*)d_in[7];
    float* out = (float*)d_out;

    void *pz, *ph, *pw1, *pw2, *pw3;
    cudaGetSymbolAddress(&pz, g_zh);
    cudaGetSymbolAddress(&ph, g_hh);
    cudaGetSymbolAddress(&pw1, g_wt1);
    cudaGetSymbolAddress(&pw2, g_wt2);
    cudaGetSymbolAddress(&pw3, g_wt3);
    __half* Z   = (__half*)pz;
    __half* H   = (__half*)ph;
    __half* Wt1 = (__half*)pw1;
    __half* Wt2 = (__half*)pw2;
    __half* Wt3 = (__half*)pw3;

    const int smem1 = (128 * (F_IN + 8) + HID   * (F_IN + 8)) * 2;  // 52224 B
    const int smem2 = (128 * (HID + 8)  + HID   * (HID + 8)) * 2;   // 27648 B
    const int smem3 = (128 * (HID + 8)  + N_CLS * (HID + 8)) * 2;   // 20736 B
    cudaFuncSetAttribute(k_mgemm<F_IN, HID, false>,
                         cudaFuncAttributeMaxDynamicSharedMemorySize, smem1);

    // graph structure + weights (recomputed every call; no caching)
    k_prep<<<(NN + 255) / 256, 256>>>((const int*)ei, W1, W2, W3);
    k_count<<<(NE / 4 + 255) / 256, 256>>>(ei);
    k_scan1<<<(NN + 1023) / 1024, 1024>>>();
    k_scan2<<<1, 128>>>((NN + 1023) / 1024);
    k_scan3<<<(NN + 255) / 256, 256>>>();
    k_fill<<<(NE / 4 + 255) / 256, 256>>>(ei);

    const int gb = (NN + 127) / 128;
    // layer 1: 128 -> 64, relu
    k_mgemm<F_IN, HID, false><<<gb, 256, smem1>>>(x, Wt1, Z);
    k_agg64<true><<<(NN * 32) / 256, 256>>>(Z, b1, H);

    // layer 2: 64 -> 64, relu
    k_mgemm<HID, HID, true><<<gb, 256, smem2>>>(H, Wt2, Z);
    k_agg64<true><<<(NN * 32) / 256, 256>>>(Z, b2, H);

    // layer 3: 64 -> 16, no relu
    k_mgemm<HID, N_CLS, true><<<gb, 256, smem3>>>(H, Wt3, Z);
    k_agg16<<<(NN * 32) / 256, 256>>>(Z, b3, out);
}